// round 15
// baseline (speedup 1.0000x reference)
#include <cuda_runtime.h>

#define NN 30
#define EPG 240
#define NEDGE 245760
#define ETOT  276480

typedef unsigned long long u64;

__device__ float g_h [30720*256];
__device__ float g_y0[30720*256];
__device__ float g_y1[30720*512];
__device__ float g_y2[30720*256];
__device__ float g_z1[1024*512];
__device__ float g_z2[1024*256];
__device__ float g_wlt[64*256];
__device__ float g_wrt[64*256];
__device__ float g_w0t[768*256];
__device__ float g_w1t[768*512];
__device__ float g_ds1t[256*512];
__device__ float g_w2t[1536*256];
__device__ float g_ds2t[512*256];
__device__ float g_fc1p[7680*512];

__device__ __forceinline__ unsigned ford(float f){
    unsigned u = __float_as_uint(f);
    return (u & 0x80000000u) ? ~u : (u | 0x80000000u);
}
__device__ __forceinline__ float finv(unsigned u){
    return __uint_as_float((u & 0x80000000u) ? (u & 0x7fffffffu) : ~u);
}

__device__ __forceinline__ u64 dup2(float v){
    u64 r; asm("mov.b64 %0, {%1, %1};" : "=l"(r) : "f"(v)); return r;
}
__device__ __forceinline__ float2 unp2(u64 v){
    float2 r; asm("mov.b64 {%0, %1}, %2;" : "=f"(r.x), "=f"(r.y) : "l"(v)); return r;
}
__device__ __forceinline__ void fma2(u64& a, u64 b, u64 c){
    asm("fma.rn.f32x2 %0, %1, %2, %0;" : "+l"(a) : "l"(b), "l"(c));
}

__device__ __forceinline__ float tf32r(float f){
    unsigned u; asm("cvt.rna.tf32.f32 %0, %1;" : "=r"(u) : "f"(f));
    return __uint_as_float(u);
}
__device__ __forceinline__ void mma8(float* d, const unsigned* a, unsigned b0, unsigned b1){
    asm("mma.sync.aligned.m16n8k8.row.col.f32.tf32.tf32.f32 "
        "{%0,%1,%2,%3},{%4,%5,%6,%7},{%8,%9},{%0,%1,%2,%3};"
        : "+f"(d[0]),"+f"(d[1]),"+f"(d[2]),"+f"(d[3])
        : "r"(a[0]),"r"(a[1]),"r"(a[2]),"r"(a[3]),"r"(b0),"r"(b1));
}

// ---- weight prep: paired layout [(tap,kk,tig)][co][2], h = (ci&7)>>2 ----
__global__ void k_tr_wlr(const float* __restrict__ wl, const float* __restrict__ wr){
    int i = blockIdx.x*256 + threadIdx.x;
    if (i < 64*256){ int c = i>>6, k = i&63; g_wlt[k*256+c] = wl[i]; g_wrt[k*256+c] = wr[i]; }
}
__global__ void k_tr_w0(const float* __restrict__ w){
    int i = blockIdx.x*256 + threadIdx.x;
    if (i < 256*768){
        int co = i/768, rem = i - co*768, ci = rem/3, t = rem - ci*3;
        int kk = ci>>3, r7 = ci&7, tig = r7&3, h = r7>>2;
        g_w0t[(((size_t)(t*32+kk)*4 + tig)*256 + co)*2 + h] = tf32r(w[i]);
    }
}
__global__ void k_tr_w1(const float* __restrict__ w){
    int i = blockIdx.x*256 + threadIdx.x;
    if (i < 512*768){
        int co = i/768, rem = i - co*768, ci = rem/3, t = rem - ci*3;
        int kk = ci>>3, r7 = ci&7, tig = r7&3, h = r7>>2;
        g_w1t[(((size_t)(t*32+kk)*4 + tig)*512 + co)*2 + h] = tf32r(w[i]);
    }
}
__global__ void k_tr_ds1(const float* __restrict__ w){
    int i = blockIdx.x*256 + threadIdx.x;
    if (i < 512*256){
        int co = i>>8, ci = i&255;
        int kk = ci>>3, r7 = ci&7, tig = r7&3, h = r7>>2;
        g_ds1t[(((size_t)kk*4 + tig)*512 + co)*2 + h] = tf32r(w[i]);
    }
}
__global__ void k_tr_w2(const float* __restrict__ w){
    int i = blockIdx.x*256 + threadIdx.x;
    if (i < 256*1536){
        int co = i/1536, rem = i - co*1536, ci = rem/3, t = rem - ci*3;
        int kk = ci>>3, r7 = ci&7, tig = r7&3, h = r7>>2;
        g_w2t[(((size_t)(t*64+kk)*4 + tig)*256 + co)*2 + h] = tf32r(w[i]);
    }
}
__global__ void k_tr_ds2(const float* __restrict__ w){
    int i = blockIdx.x*256 + threadIdx.x;
    if (i < 256*512){
        int co = i>>9, ci = i&511;
        int kk = ci>>3, r7 = ci&7, tig = r7&3, h = r7>>2;
        g_ds2t[(((size_t)kk*4 + tig)*256 + co)*2 + h] = tf32r(w[i]);
    }
}
__global__ void k_tr_fc1(const float* __restrict__ w){
    int i = blockIdx.x*256 + threadIdx.x;
    if (i < 7680*512){
        int kp = i >> 9, o = i & 511;
        int l = kp >> 8, c = kp & 255;
        int kkg = kp>>3, r7 = kp&7, tig = r7&3, h = r7>>2;
        g_fc1p[(((size_t)kkg*4 + tig)*512 + o)*2 + h] = tf32r(w[o*7680 + c*30 + l]);
    }
}
__global__ void k_ei(const int* __restrict__ eidx, float* __restrict__ eo){
    int e = blockIdx.x*256 + threadIdx.x;
    if (e < ETOT){
        float s, d;
        if (e < NEDGE){ s = (float)eidx[e]; d = (float)eidx[NEDGE+e]; }
        else          { s = d = (float)(e - NEDGE); }
        eo[e] = s; eo[ETOT + e] = d;
    }
}

// ---- GATv2 per graph (fp32; xl/xr phase in f32x2) ----
__global__ __launch_bounds__(256) void k_gat(
    const float* __restrict__ x, const float* __restrict__ bl, const float* __restrict__ br,
    const float* __restrict__ att, const float* __restrict__ bias,
    const int* __restrict__ eidx, float* __restrict__ alphaOut)
{
    extern __shared__ float sm[];
    float*    xst   = sm;              // 64*34 = 2176
    float*    xl    = xst + 2176;      // 7680
    float*    xr    = xl + 7680;       // 7680
    float*    atts  = xr + 7680;       // 256
    float*    ea    = atts + 256;      // 1088
    float*    esum  = ea + 1088;       // 120
    unsigned* emaxu = (unsigned*)(esum + 120);  // 120
    int*      srcs  = (int*)(emaxu + 120);      // 272
    int*      dsts  = srcs + 272;               // 272
    int*      cnt   = dsts + 272;               // 32
    int*      lists = cnt + 32;                 // 1440

    const int b = blockIdx.x, tid = threadIdx.x;

    for (int i = tid; i < NN*64; i += 256){
        int n = i >> 6, k = i & 63;
        xst[k*34 + n] = x[(size_t)b*NN*64 + i];
    }
    atts[tid] = att[tid];
    for (int i = tid; i < 120; i += 256){ emaxu[i] = 0u; esum[i] = 0.f; }
    if (tid < 30) cnt[tid] = 0;
    for (int j = tid; j < 270; j += 256){
        int s, d;
        if (j < EPG){
            s = eidx[(size_t)b*EPG + j] - b*NN;
            d = eidx[NEDGE + (size_t)b*EPG + j] - b*NN;
        } else { s = d = j - EPG; }
        srcs[j] = s; dsts[j] = d;
    }
    __syncthreads();

    {   // xl/xr: f32x2 over node pairs
        const int c = tid;
        u64 accl2[15], accr2[15];
        {
            u64 bl2 = dup2(bl[c]), br2 = dup2(br[c]);
            #pragma unroll
            for (int j = 0; j < 15; j++){ accl2[j] = bl2; accr2[j] = br2; }
        }
        #pragma unroll 4
        for (int kk = 0; kk < 64; kk++){
            u64 wl2 = dup2(__ldg(&g_wlt[kk*256 + c]));
            u64 wr2 = dup2(__ldg(&g_wrt[kk*256 + c]));
            const float* row = &xst[kk*34];
            #pragma unroll
            for (int j = 0; j < 15; j++){
                u64 xv = *(const u64*)(row + 2*j);
                fma2(accl2[j], wl2, xv);
                fma2(accr2[j], wr2, xv);
            }
        }
        #pragma unroll
        for (int j = 0; j < 15; j++){
            float2 pl = unp2(accl2[j]), pr = unp2(accr2[j]);
            xl[(2*j)*256 + c]   = pl.x;  xl[(2*j+1)*256 + c] = pl.y;
            xr[(2*j)*256 + c]   = pr.x;  xr[(2*j+1)*256 + c] = pr.y;
        }
    }
    __syncthreads();

    {   // edge scores
        const int warp = tid >> 5, lane = tid & 31;
        const int h4 = lane >> 3, chb = lane * 8;
        for (int e = warp; e < 270; e += 8){
            const float* pl = &xl[srcs[e]*256 + chb];
            const float* pr = &xr[dsts[e]*256 + chb];
            float p = 0.f;
            #pragma unroll
            for (int i = 0; i < 8; i++){
                float v = pl[i] + pr[i];
                v = v > 0.f ? v : 0.2f*v;
                p += v * atts[chb + i];
            }
            p += __shfl_down_sync(0xffffffffu, p, 4, 8);
            p += __shfl_down_sync(0xffffffffu, p, 2, 8);
            p += __shfl_down_sync(0xffffffffu, p, 1, 8);
            if ((lane & 7) == 0) ea[e*4 + h4] = p;
        }
    }
    __syncthreads();

    for (int it = tid; it < 1080; it += 256){
        int e = it >> 2, h = it & 3;
        atomicMax(&emaxu[dsts[e]*4 + h], ford(ea[it]));
    }
    __syncthreads();
    for (int it = tid; it < 1080; it += 256){
        int e = it >> 2, h = it & 3; int d = dsts[e];
        float ex = __expf(ea[it] - finv(emaxu[d*4 + h]));
        ea[it] = ex;
        atomicAdd(&esum[d*4 + h], ex);
    }
    __syncthreads();
    for (int it = tid; it < 1080; it += 256){
        int e = it >> 2, h = it & 3;
        float a = ea[it] / esum[dsts[e]*4 + h];
        ea[it] = a;
        if (alphaOut){
            int grow = (e < EPG) ? (b*EPG + e) : (NEDGE + b*NN + (e - EPG));
            alphaOut[(size_t)grow*4 + h] = a;
        }
    }
    for (int e = tid; e < 270; e += 256){
        int d = dsts[e];
        int slot = atomicAdd(&cnt[d], 1);
        if (slot < 48) lists[d*48 + slot] = e;
    }
    __syncthreads();

    {   // aggregate
        const int c = tid, hh = c >> 6;
        float bv = bias[c];
        for (int n = 0; n < NN; n++){
            float a = 0.f;
            int deg = cnt[n]; if (deg > 48) deg = 48;
            for (int i = 0; i < deg; i++){
                int e = lists[n*48 + i];
                a += ea[e*4 + hh] * xl[srcs[e]*256 + c];
            }
            float v = a + bv;
            g_h[((size_t)(b*NN + n))*256 + c] = v > 0.f ? v : 0.f;
        }
    }
}

// ==================== TF32 mma TCN conv: paired-k A tile (LDS.64) + paired weights ====================
// hsp layout: [(gg, kk, tig)-row][l (R slots)][2], pair = channels (kk*8+tig, kk*8+tig+4).
// One LDS.64 = fragment pair {A0,A2}; second = {A1,A3}. 8 LDS.64/kk vs 16 LDS.32.
template<int CIN, int COUT, int DIL, int NCHUNK, int THREADS, bool HAS_DS>
__device__ __forceinline__ void tcn_mma(
    const float* __restrict__ srcY, const float* __restrict__ Wt, const float* __restrict__ Wds,
    const float* __restrict__ dsb,
    const float* __restrict__ lnw, const float* __restrict__ lnb,
    const float* __restrict__ resSrc, float* __restrict__ dstY)
{
    const int R = 40;                  // l-slots per row (in 8-byte pair units)
    const int NWARP = THREADS/32;
    const int NT = NCHUNK/(NWARP*8);
    const int KS = CIN/8;
    const int ROWSG = CIN/2;           // (KS*4) paired rows per graph
    extern __shared__ float smem[];
    float* hsp = smem;                 // 2*ROWSG*R*2 floats = 2*CIN*R

    const int tid  = threadIdx.x;
    const int warp = tid >> 5, lane = tid & 31;
    const int g = lane >> 2, tig = lane & 3;
    const int b0g = blockIdx.x*2;

    for (int i = tid; i < 2*CIN*R; i += THREADS) hsp[i] = 0.f;
    __syncthreads();
    for (int idx = tid; idx < 2*30*CIN; idx += THREADS){
        int gg = idx / (30*CIN); int r = idx - gg*30*CIN;
        int l = r / CIN, c = r - l*CIN;
        int kk = c>>3, r7 = c&7, tg = r7&3, h = r7>>2;
        int rw = gg*ROWSG + kk*4 + tg;
        hsp[((size_t)rw*R + DIL + l)*2 + h] =
            tf32r(srcY[((size_t)((b0g+gg)*30) + l)*CIN + c]);
    }
    __syncthreads();

    float lnw4[4], lnb4[4];
    #pragma unroll
    for (int idx = 0; idx < 4; idx++){
        int l = g + 8*idx;
        lnw4[idx] = (l < 30) ? __ldg(&lnw[l]) : 0.f;
        lnb4[idx] = (l < 30) ? __ldg(&lnb[l]) : 0.f;
    }

    for (int chunk = 0; chunk < COUT/NCHUNK; chunk++){
        const int nbase = chunk*NCHUNK + warp*(NCHUNK/NWARP);
        float acc[4][NT][4];
        float accd[HAS_DS?4:1][NT][4];
        #pragma unroll
        for (int mt=0; mt<4; mt++)
            #pragma unroll
            for (int nt=0; nt<NT; nt++)
                #pragma unroll
                for (int q=0; q<4; q++){
                    acc[mt][nt][q] = 0.f;
                    if (HAS_DS) accd[mt][nt][q] = 0.f;
                }

        #pragma unroll
        for (int t = 0; t < 3; t++){
            const int aoff = DIL*t;
            #pragma unroll 2
            for (int kk = 0; kk < KS; kk++){
                unsigned A[4][4];
                #pragma unroll
                for (int mt=0; mt<4; mt++){
                    int rw = (mt>>1)*ROWSG + kk*4 + tig;
                    const u64* base = (const u64*)&hsp[((size_t)rw*R + aoff + (mt&1)*16 + g)*2];
                    u64 lo = base[0];         // {A0, A2}
                    u64 hi = base[8];         // rows l+8 -> {A1, A3}
                    A[mt][0] = (unsigned)lo;  A[mt][2] = (unsigned)(lo >> 32);
                    A[mt][1] = (unsigned)hi;  A[mt][3] = (unsigned)(hi >> 32);
                }
                const float* Wp = Wt + ((size_t)((t*KS + kk)*4 + tig)*COUT + nbase)*2;
                #pragma unroll
                for (int nt=0; nt<NT; nt++){
                    u64 wv = __ldg((const u64*)(Wp + (nt*8 + g)*2));
                    unsigned br0 = (unsigned)wv, br1 = (unsigned)(wv >> 32);
                    #pragma unroll
                    for (int mt=0; mt<4; mt++) mma8(acc[mt][nt], A[mt], br0, br1);
                }
                if (HAS_DS && t == 1){
                    const float* Wdp = Wds + ((size_t)(kk*4 + tig)*COUT + nbase)*2;
                    #pragma unroll
                    for (int nt=0; nt<NT; nt++){
                        u64 wv = __ldg((const u64*)(Wdp + (nt*8 + g)*2));
                        unsigned br0 = (unsigned)wv, br1 = (unsigned)(wv >> 32);
                        #pragma unroll
                        for (int mt=0; mt<4; mt++) mma8(accd[mt][nt], A[mt], br0, br1);
                    }
                }
            }
        }

        // ---- shuffle-LN epilogue ----
        #pragma unroll
        for (int gg = 0; gg < 2; gg++){
            #pragma unroll
            for (int nt = 0; nt < NT; nt++){
                const int colb = nbase + nt*8 + 2*tig;
                float sx = 0.f, sy = 0.f;
                #pragma unroll
                for (int p = 0; p < 2; p++)
                    #pragma unroll
                    for (int q = 0; q < 4; q++){
                        int idx = (q>>1) + 2*p;
                        bool valid = (idx < 3) || (g < 6);
                        if (valid){
                            float val = acc[2*gg+p][nt][q];
                            if (q & 1) sy += val; else sx += val;
                        }
                    }
                #pragma unroll
                for (int off = 4; off < 32; off <<= 1){
                    sx += __shfl_xor_sync(0xffffffffu, sx, off);
                    sy += __shfl_xor_sync(0xffffffffu, sy, off);
                }
                float mux = sx*(1.f/30.f), muy = sy*(1.f/30.f);
                float vx = 0.f, vy = 0.f;
                #pragma unroll
                for (int p = 0; p < 2; p++)
                    #pragma unroll
                    for (int q = 0; q < 4; q++){
                        int idx = (q>>1) + 2*p;
                        bool valid = (idx < 3) || (g < 6);
                        if (valid){
                            float val = acc[2*gg+p][nt][q];
                            if (q & 1){ float d = val - muy; vy += d*d; }
                            else      { float d = val - mux; vx += d*d; }
                        }
                    }
                #pragma unroll
                for (int off = 4; off < 32; off <<= 1){
                    vx += __shfl_xor_sync(0xffffffffu, vx, off);
                    vy += __shfl_xor_sync(0xffffffffu, vy, off);
                }
                float rsx = rsqrtf(vx*(1.f/30.f) + 1e-5f);
                float rsy = rsqrtf(vy*(1.f/30.f) + 1e-5f);
                float dbv0 = 0.f, dbv1 = 0.f;
                if (HAS_DS){ dbv0 = __ldg(&dsb[colb]); dbv1 = __ldg(&dsb[colb+1]); }
                #pragma unroll
                for (int p = 0; p < 2; p++)
                    #pragma unroll
                    for (int h = 0; h < 2; h++){
                        int idx = h + 2*p;
                        int l = g + 8*idx;
                        if (l < 30){
                            float o0 = (acc[2*gg+p][nt][2*h]   - mux)*rsx*lnw4[idx] + lnb4[idx];
                            float o1 = (acc[2*gg+p][nt][2*h+1] - muy)*rsy*lnw4[idx] + lnb4[idx];
                            o0 = o0 > 0.f ? o0 : 0.f;
                            o1 = o1 > 0.f ? o1 : 0.f;
                            float r0, r1;
                            if (HAS_DS){
                                r0 = accd[2*gg+p][nt][2*h]   + dbv0;
                                r1 = accd[2*gg+p][nt][2*h+1] + dbv1;
                            } else {
                                float2 rr = *(const float2*)&resSrc[((size_t)((b0g+gg)*30) + l)*COUT + colb];
                                r0 = rr.x; r1 = rr.y;
                            }
                            float2 o; o.x = o0 + r0; o.y = o1 + r1;
                            *(float2*)&dstY[((size_t)((b0g+gg)*30) + l)*COUT + colb] = o;
                        }
                    }
            }
        }
    }
}

__global__ __launch_bounds__(512,1) void k_tcn0m(const float* __restrict__ lnw, const float* __restrict__ lnb){
    tcn_mma<256,256,1,256,512,false>(g_h, g_w0t, nullptr, nullptr, lnw, lnb, g_h, g_y0);
}
__global__ __launch_bounds__(512,1) void k_tcn1m(const float* __restrict__ dsb,
    const float* __restrict__ lnw, const float* __restrict__ lnb){
    tcn_mma<256,512,2,256,512,true>(g_y0, g_w1t, g_ds1t, dsb, lnw, lnb, nullptr, g_y1);
}
__global__ __launch_bounds__(512,1) void k_tcn2m(const float* __restrict__ dsb,
    const float* __restrict__ lnw, const float* __restrict__ lnb){
    tcn_mma<512,256,4,256,512,true>(g_y1, g_w2t, g_ds2t, dsb, lnw, lnb, nullptr, g_y2);
}

// ==================== generic TF32 mma GEMM (fc1), paired weights ====================
template<int K, int N, bool RELU>
__device__ __forceinline__ void mm_body(const float* __restrict__ A, const float* __restrict__ W,
    const float* __restrict__ bias, float* __restrict__ C)
{
    __shared__ __align__(16) float As[64][68];
    const int tid = threadIdx.x;
    const int warp = tid >> 5, lane = tid & 31;
    const int g = lane >> 2, tig = lane & 3;
    const int m0 = blockIdx.y*64, n0 = blockIdx.x*128;

    float acc[4][2][4];
    #pragma unroll
    for (int mt=0; mt<4; mt++)
        #pragma unroll
        for (int nt=0; nt<2; nt++)
            #pragma unroll
            for (int q=0; q<4; q++) acc[mt][nt][q] = 0.f;

    const int r = tid >> 2, cq = (tid & 3)*16;
    for (int k0 = 0; k0 < K; k0 += 64){
        __syncthreads();
        #pragma unroll
        for (int j = 0; j < 4; j++){
            float4 v = *(const float4*)&A[(size_t)(m0+r)*K + k0 + cq + j*4];
            As[r][cq+j*4+0] = tf32r(v.x); As[r][cq+j*4+1] = tf32r(v.y);
            As[r][cq+j*4+2] = tf32r(v.z); As[r][cq+j*4+3] = tf32r(v.w);
        }
        __syncthreads();
        #pragma unroll 2
        for (int kk = 0; kk < 8; kk++){
            unsigned Af[4][4];
            #pragma unroll
            for (int mt=0; mt<4; mt++){
                const float* base = &As[mt*16+g][kk*8+tig];
                Af[mt][0] = __float_as_uint(base[0]);
                Af[mt][1] = __float_as_uint(base[8*68]);
                Af[mt][2] = __float_as_uint(base[4]);
                Af[mt][3] = __float_as_uint(base[8*68+4]);
            }
            const float* Wp = W + ((size_t)(((k0>>3) + kk)*4 + tig)*N + n0 + warp*16)*2;
            #pragma unroll
            for (int nt=0; nt<2; nt++){
                u64 wv = __ldg((const u64*)(Wp + (nt*8 + g)*2));
                unsigned br0 = (unsigned)wv, br1 = (unsigned)(wv >> 32);
                #pragma unroll
                for (int mt=0; mt<4; mt++) mma8(acc[mt][nt], Af[mt], br0, br1);
            }
        }
    }
    #pragma unroll
    for (int mt=0; mt<4; mt++)
        #pragma unroll
        for (int nt=0; nt<2; nt++){
            int colb = n0 + warp*16 + nt*8 + 2*tig;
            float b0 = __ldg(&bias[colb]), b1 = __ldg(&bias[colb+1]);
            #pragma unroll
            for (int h2=0; h2<2; h2++){
                int row = m0 + mt*16 + g + 8*h2;
                float v0 = acc[mt][nt][2*h2]   + b0;
                float v1 = acc[mt][nt][2*h2+1] + b1;
                if (RELU){ v0 = v0 > 0.f ? v0 : 0.f; v1 = v1 > 0.f ? v1 : 0.f; }
                float2 o; o.x = v0; o.y = v1;
                *(float2*)&C[(size_t)row*N + colb] = o;
            }
        }
}
__global__ __launch_bounds__(256) void k_fc1mm(const float* __restrict__ bias){
    mm_body<7680,512,true>(g_y2, g_fc1p, bias, g_z1);
}

// ---- f32x2 tiled GEMM for fc2/fc3 ----
__device__ __forceinline__ void gemm_body(const float* __restrict__ A, const float* __restrict__ Bw,
    const float* __restrict__ bias, float* __restrict__ C, int M, int N, int K, bool doRelu)
{
    __shared__ __align__(16) float As2[16][68];
    __shared__ __align__(16) float Bs2[16][68];
    const int tid = threadIdx.x;
    const int tx = tid & 15, ty = tid >> 4;
    const int m0 = blockIdx.y*64, n0 = blockIdx.x*64;
    const int lm = tid >> 2, lk = (tid & 3)*4;
    u64 acc2[4][2];
    #pragma unroll
    for (int i = 0; i < 4; i++){ acc2[i][0] = 0ull; acc2[i][1] = 0ull; }

    for (int k0 = 0; k0 < K; k0 += 16){
        float4 av = *(const float4*)&A[(size_t)(m0+lm)*K + k0 + lk];
        float4 bv = make_float4(0.f,0.f,0.f,0.f);
        if (n0 + lm < N) bv = *(const float4*)&Bw[(size_t)(n0+lm)*K + k0 + lk];
        As2[lk+0][lm] = av.x; As2[lk+1][lm] = av.y; As2[lk+2][lm] = av.z; As2[lk+3][lm] = av.w;
        Bs2[lk+0][lm] = bv.x; Bs2[lk+1][lm] = bv.y; Bs2[lk+2][lm] = bv.z; Bs2[lk+3][lm] = bv.w;
        __syncthreads();
        #pragma unroll
        for (int k = 0; k < 16; k++){
            float4 a = *(const float4*)&As2[k][ty*4];
            u64 bp0 = *(const u64*)&Bs2[k][tx*4];
            u64 bp1 = *(const u64*)&Bs2[k][tx*4+2];
            u64 a0 = dup2(a.x), a1 = dup2(a.y), a2 = dup2(a.z), a3 = dup2(a.w);
            fma2(acc2[0][0], a0, bp0); fma2(acc2[0][1], a0, bp1);
            fma2(acc2[1][0], a1, bp0); fma2(acc2[1][1], a1, bp1);
            fma2(acc2[2][0], a2, bp0); fma2(acc2[2][1], a2, bp1);
            fma2(acc2[3][0], a3, bp0); fma2(acc2[3][1], a3, bp1);
        }
        __syncthreads();
    }
    #pragma unroll
    for (int i = 0; i < 4; i++){
        int row = m0 + ty*4 + i;
        float2 p0 = unp2(acc2[i][0]), p1 = unp2(acc2[i][1]);
        float vals[4] = {p0.x, p0.y, p1.x, p1.y};
        #pragma unroll
        for (int j = 0; j < 4; j++){
            int col = n0 + tx*4 + j;
            if (col < N){
                float v = vals[j] + __ldg(&bias[col]);
                if (doRelu) v = v > 0.f ? v : 0.f;
                C[(size_t)row*N + col] = v;
            }
        }
    }
}
__global__ __launch_bounds__(256) void k_fc2(const float* __restrict__ w, const float* __restrict__ bias){
    gemm_body(g_z1, w, bias, g_z2, 1024, 256, 512, true);
}
__global__ __launch_bounds__(256) void k_fc3(const float* __restrict__ w, const float* __restrict__ bias,
                                             float* __restrict__ out){
    gemm_body(g_z2, w, bias, out, 1024, 144, 256, false);
}

extern "C" void kernel_launch(void* const* d_in, const int* in_sizes, int n_in,
                              void* d_out, int out_size) {
    const float* x      = (const float*)d_in[0];
    const float* gWl    = (const float*)d_in[1];
    const float* gbl    = (const float*)d_in[2];
    const float* gWr    = (const float*)d_in[3];
    const float* gbr    = (const float*)d_in[4];
    const float* gatt   = (const float*)d_in[5];
    const float* gbias  = (const float*)d_in[6];
    const float* t0w    = (const float*)d_in[7];
    const float* ln0w   = (const float*)d_in[9];
    const float* ln0b   = (const float*)d_in[10];
    const float* t1w    = (const float*)d_in[11];
    const float* ln1w   = (const float*)d_in[13];
    const float* ln1b   = (const float*)d_in[14];
    const float* ds1w   = (const float*)d_in[15];
    const float* ds1b   = (const float*)d_in[16];
    const float* t2w    = (const float*)d_in[17];
    const float* ln2w   = (const float*)d_in[19];
    const float* ln2b   = (const float*)d_in[20];
    const float* ds2w   = (const float*)d_in[21];
    const float* ds2b   = (const float*)d_in[22];
    const float* fc1w   = (const float*)d_in[23];
    const float* fc1b   = (const float*)d_in[24];
    const float* fc2w   = (const float*)d_in[25];
    const float* fc2b   = (const float*)d_in[26];
    const float* fc3w   = (const float*)d_in[27];
    const float* fc3b   = (const float*)d_in[28];
    const int*   eidx   = (const int*)d_in[29];

    float* outp = (float*)d_out;
    bool full = (out_size >= 147456 + ETOT*4 + 2*ETOT);
    float* alphaOut = full ? (outp + 147456) : nullptr;
    float* eiOut    = full ? (outp + 147456 + ETOT*4) : nullptr;

    const int SM01 = 2*256*40*4;   // 81,920
    const int SM2  = 2*512*40*4;   // 163,840

    cudaFuncSetAttribute(k_gat,   cudaFuncAttributeMaxDynamicSharedMemorySize, 85*1024);
    cudaFuncSetAttribute(k_tcn0m, cudaFuncAttributeMaxDynamicSharedMemorySize, SM01);
    cudaFuncSetAttribute(k_tcn1m, cudaFuncAttributeMaxDynamicSharedMemorySize, SM01);
    cudaFuncSetAttribute(k_tcn2m, cudaFuncAttributeMaxDynamicSharedMemorySize, SM2);

    k_tr_wlr<<<64,256>>>(gWl, gWr);
    k_tr_w0 <<<768,256>>>(t0w);
    k_tr_w1 <<<1536,256>>>(t1w);
    k_tr_ds1<<<512,256>>>(ds1w);
    k_tr_w2 <<<1536,256>>>(t2w);
    k_tr_ds2<<<512,256>>>(ds2w);
    k_tr_fc1<<<15360,256>>>(fc1w);
    if (eiOut) k_ei<<<1080,256>>>(eidx, eiOut);

    k_gat<<<1024,256, 85*1024>>>(x, gbl, gbr, gatt, gbias, eidx, alphaOut);
    k_tcn0m<<<512,512, SM01>>>(ln0w, ln0b);
    k_tcn1m<<<512,512, SM01>>>(ds1b, ln1w, ln1b);
    k_tcn2m<<<512,512, SM2>>>(ds2b, ln2w, ln2b);

    { dim3 gd(4,16);  k_fc1mm<<<gd,256>>>(fc1b); }
    dim3 g2(4,16);  k_fc2<<<g2,256>>>(fc2w, fc2b);
    dim3 g3(3,16);  k_fc3<<<g3,256>>>(fc3w, fc3b, outp);
}

// round 16
// speedup vs baseline: 1.1336x; 1.1336x over previous
#include <cuda_runtime.h>

#define NN 30
#define EPG 240
#define NEDGE 245760
#define ETOT  276480

typedef unsigned long long u64;

__device__ float g_h [30720*256];
__device__ float g_y0[30720*256];
__device__ float g_y1[30720*512];
__device__ float g_y2[30720*256];
__device__ float g_z1[1024*512];
__device__ float g_z2[1024*256];
__device__ float g_wlt[64*256];
__device__ float g_wrt[64*256];
__device__ float g_w0t[768*256];
__device__ float g_w1t[768*512];
__device__ float g_ds1t[256*512];
__device__ float g_w2t[1536*256];
__device__ float g_ds2t[512*256];
__device__ float g_fc1p[7680*512];

__device__ __forceinline__ unsigned ford(float f){
    unsigned u = __float_as_uint(f);
    return (u & 0x80000000u) ? ~u : (u | 0x80000000u);
}
__device__ __forceinline__ float finv(unsigned u){
    return __uint_as_float((u & 0x80000000u) ? (u & 0x7fffffffu) : ~u);
}

__device__ __forceinline__ u64 dup2(float v){
    u64 r; asm("mov.b64 %0, {%1, %1};" : "=l"(r) : "f"(v)); return r;
}
__device__ __forceinline__ float2 unp2(u64 v){
    float2 r; asm("mov.b64 {%0, %1}, %2;" : "=f"(r.x), "=f"(r.y) : "l"(v)); return r;
}
__device__ __forceinline__ void fma2(u64& a, u64 b, u64 c){
    asm("fma.rn.f32x2 %0, %1, %2, %0;" : "+l"(a) : "l"(b), "l"(c));
}

__device__ __forceinline__ float tf32r(float f){
    unsigned u; asm("cvt.rna.tf32.f32 %0, %1;" : "=r"(u) : "f"(f));
    return __uint_as_float(u);
}
__device__ __forceinline__ void mma8(float* d, const unsigned* a, unsigned b0, unsigned b1){
    asm("mma.sync.aligned.m16n8k8.row.col.f32.tf32.tf32.f32 "
        "{%0,%1,%2,%3},{%4,%5,%6,%7},{%8,%9},{%0,%1,%2,%3};"
        : "+f"(d[0]),"+f"(d[1]),"+f"(d[2]),"+f"(d[3])
        : "r"(a[0]),"r"(a[1]),"r"(a[2]),"r"(a[3]),"r"(b0),"r"(b1));
}

// ---- weight prep: paired layout [(tap,kk,tig)][co][2], h = (ci&7)>>2 ----
__global__ void k_tr_wlr(const float* __restrict__ wl, const float* __restrict__ wr){
    int i = blockIdx.x*256 + threadIdx.x;
    if (i < 64*256){ int c = i>>6, k = i&63; g_wlt[k*256+c] = wl[i]; g_wrt[k*256+c] = wr[i]; }
}
__global__ void k_tr_w0(const float* __restrict__ w){
    int i = blockIdx.x*256 + threadIdx.x;
    if (i < 256*768){
        int co = i/768, rem = i - co*768, ci = rem/3, t = rem - ci*3;
        int kk = ci>>3, r7 = ci&7, tig = r7&3, h = r7>>2;
        g_w0t[(((size_t)(t*32+kk)*4 + tig)*256 + co)*2 + h] = tf32r(w[i]);
    }
}
__global__ void k_tr_w1(const float* __restrict__ w){
    int i = blockIdx.x*256 + threadIdx.x;
    if (i < 512*768){
        int co = i/768, rem = i - co*768, ci = rem/3, t = rem - ci*3;
        int kk = ci>>3, r7 = ci&7, tig = r7&3, h = r7>>2;
        g_w1t[(((size_t)(t*32+kk)*4 + tig)*512 + co)*2 + h] = tf32r(w[i]);
    }
}
__global__ void k_tr_ds1(const float* __restrict__ w){
    int i = blockIdx.x*256 + threadIdx.x;
    if (i < 512*256){
        int co = i>>8, ci = i&255;
        int kk = ci>>3, r7 = ci&7, tig = r7&3, h = r7>>2;
        g_ds1t[(((size_t)kk*4 + tig)*512 + co)*2 + h] = tf32r(w[i]);
    }
}
__global__ void k_tr_w2(const float* __restrict__ w){
    int i = blockIdx.x*256 + threadIdx.x;
    if (i < 256*1536){
        int co = i/1536, rem = i - co*1536, ci = rem/3, t = rem - ci*3;
        int kk = ci>>3, r7 = ci&7, tig = r7&3, h = r7>>2;
        g_w2t[(((size_t)(t*64+kk)*4 + tig)*256 + co)*2 + h] = tf32r(w[i]);
    }
}
__global__ void k_tr_ds2(const float* __restrict__ w){
    int i = blockIdx.x*256 + threadIdx.x;
    if (i < 256*512){
        int co = i>>9, ci = i&511;
        int kk = ci>>3, r7 = ci&7, tig = r7&3, h = r7>>2;
        g_ds2t[(((size_t)kk*4 + tig)*256 + co)*2 + h] = tf32r(w[i]);
    }
}
__global__ void k_tr_fc1(const float* __restrict__ w){
    int i = blockIdx.x*256 + threadIdx.x;
    if (i < 7680*512){
        int kp = i >> 9, o = i & 511;
        int l = kp >> 8, c = kp & 255;
        int kkg = kp>>3, r7 = kp&7, tig = r7&3, h = r7>>2;
        g_fc1p[(((size_t)kkg*4 + tig)*512 + o)*2 + h] = tf32r(w[o*7680 + c*30 + l]);
    }
}
__global__ void k_ei(const int* __restrict__ eidx, float* __restrict__ eo){
    int e = blockIdx.x*256 + threadIdx.x;
    if (e < ETOT){
        float s, d;
        if (e < NEDGE){ s = (float)eidx[e]; d = (float)eidx[NEDGE+e]; }
        else          { s = d = (float)(e - NEDGE); }
        eo[e] = s; eo[ETOT + e] = d;
    }
}

// ---- GATv2 per graph (fp32; xl/xr phase in f32x2) ----
__global__ __launch_bounds__(256) void k_gat(
    const float* __restrict__ x, const float* __restrict__ bl, const float* __restrict__ br,
    const float* __restrict__ att, const float* __restrict__ bias,
    const int* __restrict__ eidx, float* __restrict__ alphaOut)
{
    extern __shared__ float sm[];
    float*    xst   = sm;              // 64*34 = 2176
    float*    xl    = xst + 2176;      // 7680
    float*    xr    = xl + 7680;       // 7680
    float*    atts  = xr + 7680;       // 256
    float*    ea    = atts + 256;      // 1088
    float*    esum  = ea + 1088;       // 120
    unsigned* emaxu = (unsigned*)(esum + 120);  // 120
    int*      srcs  = (int*)(emaxu + 120);      // 272
    int*      dsts  = srcs + 272;               // 272
    int*      cnt   = dsts + 272;               // 32
    int*      lists = cnt + 32;                 // 1440

    const int b = blockIdx.x, tid = threadIdx.x;

    for (int i = tid; i < NN*64; i += 256){
        int n = i >> 6, k = i & 63;
        xst[k*34 + n] = x[(size_t)b*NN*64 + i];
    }
    atts[tid] = att[tid];
    for (int i = tid; i < 120; i += 256){ emaxu[i] = 0u; esum[i] = 0.f; }
    if (tid < 30) cnt[tid] = 0;
    for (int j = tid; j < 270; j += 256){
        int s, d;
        if (j < EPG){
            s = eidx[(size_t)b*EPG + j] - b*NN;
            d = eidx[NEDGE + (size_t)b*EPG + j] - b*NN;
        } else { s = d = j - EPG; }
        srcs[j] = s; dsts[j] = d;
    }
    __syncthreads();

    {   // xl/xr: f32x2 over node pairs
        const int c = tid;
        u64 accl2[15], accr2[15];
        {
            u64 bl2 = dup2(bl[c]), br2 = dup2(br[c]);
            #pragma unroll
            for (int j = 0; j < 15; j++){ accl2[j] = bl2; accr2[j] = br2; }
        }
        #pragma unroll 4
        for (int kk = 0; kk < 64; kk++){
            u64 wl2 = dup2(__ldg(&g_wlt[kk*256 + c]));
            u64 wr2 = dup2(__ldg(&g_wrt[kk*256 + c]));
            const float* row = &xst[kk*34];
            #pragma unroll
            for (int j = 0; j < 15; j++){
                u64 xv = *(const u64*)(row + 2*j);
                fma2(accl2[j], wl2, xv);
                fma2(accr2[j], wr2, xv);
            }
        }
        #pragma unroll
        for (int j = 0; j < 15; j++){
            float2 pl = unp2(accl2[j]), pr = unp2(accr2[j]);
            xl[(2*j)*256 + c]   = pl.x;  xl[(2*j+1)*256 + c] = pl.y;
            xr[(2*j)*256 + c]   = pr.x;  xr[(2*j+1)*256 + c] = pr.y;
        }
    }
    __syncthreads();

    {   // edge scores
        const int warp = tid >> 5, lane = tid & 31;
        const int h4 = lane >> 3, chb = lane * 8;
        for (int e = warp; e < 270; e += 8){
            const float* pl = &xl[srcs[e]*256 + chb];
            const float* pr = &xr[dsts[e]*256 + chb];
            float p = 0.f;
            #pragma unroll
            for (int i = 0; i < 8; i++){
                float v = pl[i] + pr[i];
                v = v > 0.f ? v : 0.2f*v;
                p += v * atts[chb + i];
            }
            p += __shfl_down_sync(0xffffffffu, p, 4, 8);
            p += __shfl_down_sync(0xffffffffu, p, 2, 8);
            p += __shfl_down_sync(0xffffffffu, p, 1, 8);
            if ((lane & 7) == 0) ea[e*4 + h4] = p;
        }
    }
    __syncthreads();

    for (int it = tid; it < 1080; it += 256){
        int e = it >> 2, h = it & 3;
        atomicMax(&emaxu[dsts[e]*4 + h], ford(ea[it]));
    }
    __syncthreads();
    for (int it = tid; it < 1080; it += 256){
        int e = it >> 2, h = it & 3; int d = dsts[e];
        float ex = __expf(ea[it] - finv(emaxu[d*4 + h]));
        ea[it] = ex;
        atomicAdd(&esum[d*4 + h], ex);
    }
    __syncthreads();
    for (int it = tid; it < 1080; it += 256){
        int e = it >> 2, h = it & 3;
        float a = ea[it] / esum[dsts[e]*4 + h];
        ea[it] = a;
        if (alphaOut){
            int grow = (e < EPG) ? (b*EPG + e) : (NEDGE + b*NN + (e - EPG));
            alphaOut[(size_t)grow*4 + h] = a;
        }
    }
    for (int e = tid; e < 270; e += 256){
        int d = dsts[e];
        int slot = atomicAdd(&cnt[d], 1);
        if (slot < 48) lists[d*48 + slot] = e;
    }
    __syncthreads();

    {   // aggregate
        const int c = tid, hh = c >> 6;
        float bv = bias[c];
        for (int n = 0; n < NN; n++){
            float a = 0.f;
            int deg = cnt[n]; if (deg > 48) deg = 48;
            for (int i = 0; i < deg; i++){
                int e = lists[n*48 + i];
                a += ea[e*4 + hh] * xl[srcs[e]*256 + c];
            }
            float v = a + bv;
            g_h[((size_t)(b*NN + n))*256 + c] = v > 0.f ? v : 0.f;
        }
    }
}

// ==================== TF32 mma TCN conv + fused DS, paired LDG.64 weights ====================
template<int CIN, int COUT, int DIL, int NCHUNK, int THREADS, bool HAS_DS>
__device__ __forceinline__ void tcn_mma(
    const float* __restrict__ srcY, const float* __restrict__ Wt, const float* __restrict__ Wds,
    const float* __restrict__ dsb,
    const float* __restrict__ lnw, const float* __restrict__ lnb,
    const float* __restrict__ resSrc, float* __restrict__ dstY)
{
    const int R = 40;
    const int NWARP = THREADS/32;
    const int NT = NCHUNK/(NWARP*8);
    const int KS = CIN/8;
    extern __shared__ float smem[];
    float* hsp = smem;

    const int tid  = threadIdx.x;
    const int warp = tid >> 5, lane = tid & 31;
    const int g = lane >> 2, tig = lane & 3;
    const int b0g = blockIdx.x*2;

    for (int i = tid; i < 2*CIN*R; i += THREADS) hsp[i] = 0.f;
    __syncthreads();
    for (int idx = tid; idx < 2*30*CIN; idx += THREADS){
        int gg = idx / (30*CIN); int r = idx - gg*30*CIN;
        int l = r / CIN, c = r - l*CIN;
        hsp[(gg*CIN + c)*R + DIL + l] = tf32r(srcY[((size_t)((b0g+gg)*30) + l)*CIN + c]);
    }
    __syncthreads();

    float lnw4[4], lnb4[4];
    #pragma unroll
    for (int idx = 0; idx < 4; idx++){
        int l = g + 8*idx;
        lnw4[idx] = (l < 30) ? __ldg(&lnw[l]) : 0.f;
        lnb4[idx] = (l < 30) ? __ldg(&lnb[l]) : 0.f;
    }

    for (int chunk = 0; chunk < COUT/NCHUNK; chunk++){
        const int nbase = chunk*NCHUNK + warp*(NCHUNK/NWARP);
        float acc[4][NT][4];
        float accd[HAS_DS?4:1][NT][4];
        #pragma unroll
        for (int mt=0; mt<4; mt++)
            #pragma unroll
            for (int nt=0; nt<NT; nt++)
                #pragma unroll
                for (int q=0; q<4; q++){
                    acc[mt][nt][q] = 0.f;
                    if (HAS_DS) accd[mt][nt][q] = 0.f;
                }

        #pragma unroll
        for (int t = 0; t < 3; t++){
            const int aoff = DIL*t;
            #pragma unroll 2
            for (int kk = 0; kk < KS; kk++){
                unsigned A[4][4];
                #pragma unroll
                for (int mt=0; mt<4; mt++){
                    const float* base = &hsp[((mt>>1)*CIN + kk*8 + tig)*R + aoff + (mt&1)*16 + g];
                    A[mt][0] = __float_as_uint(base[0]);
                    A[mt][1] = __float_as_uint(base[8]);
                    A[mt][2] = __float_as_uint(base[4*R]);
                    A[mt][3] = __float_as_uint(base[4*R + 8]);
                }
                const float* Wp = Wt + ((size_t)((t*KS + kk)*4 + tig)*COUT + nbase)*2;
                #pragma unroll
                for (int nt=0; nt<NT; nt++){
                    u64 wv = __ldg((const u64*)(Wp + (nt*8 + g)*2));
                    unsigned br0 = (unsigned)wv, br1 = (unsigned)(wv >> 32);
                    #pragma unroll
                    for (int mt=0; mt<4; mt++) mma8(acc[mt][nt], A[mt], br0, br1);
                }
                if (HAS_DS && t == 1){
                    const float* Wdp = Wds + ((size_t)(kk*4 + tig)*COUT + nbase)*2;
                    #pragma unroll
                    for (int nt=0; nt<NT; nt++){
                        u64 wv = __ldg((const u64*)(Wdp + (nt*8 + g)*2));
                        unsigned br0 = (unsigned)wv, br1 = (unsigned)(wv >> 32);
                        #pragma unroll
                        for (int mt=0; mt<4; mt++) mma8(accd[mt][nt], A[mt], br0, br1);
                    }
                }
            }
        }

        // ---- shuffle-LN epilogue ----
        #pragma unroll
        for (int gg = 0; gg < 2; gg++){
            #pragma unroll
            for (int nt = 0; nt < NT; nt++){
                const int colb = nbase + nt*8 + 2*tig;
                float sx = 0.f, sy = 0.f;
                #pragma unroll
                for (int p = 0; p < 2; p++)
                    #pragma unroll
                    for (int q = 0; q < 4; q++){
                        int idx = (q>>1) + 2*p;
                        bool valid = (idx < 3) || (g < 6);
                        if (valid){
                            float val = acc[2*gg+p][nt][q];
                            if (q & 1) sy += val; else sx += val;
                        }
                    }
                #pragma unroll
                for (int off = 4; off < 32; off <<= 1){
                    sx += __shfl_xor_sync(0xffffffffu, sx, off);
                    sy += __shfl_xor_sync(0xffffffffu, sy, off);
                }
                float mux = sx*(1.f/30.f), muy = sy*(1.f/30.f);
                float vx = 0.f, vy = 0.f;
                #pragma unroll
                for (int p = 0; p < 2; p++)
                    #pragma unroll
                    for (int q = 0; q < 4; q++){
                        int idx = (q>>1) + 2*p;
                        bool valid = (idx < 3) || (g < 6);
                        if (valid){
                            float val = acc[2*gg+p][nt][q];
                            if (q & 1){ float d = val - muy; vy += d*d; }
                            else      { float d = val - mux; vx += d*d; }
                        }
                    }
                #pragma unroll
                for (int off = 4; off < 32; off <<= 1){
                    vx += __shfl_xor_sync(0xffffffffu, vx, off);
                    vy += __shfl_xor_sync(0xffffffffu, vy, off);
                }
                float rsx = rsqrtf(vx*(1.f/30.f) + 1e-5f);
                float rsy = rsqrtf(vy*(1.f/30.f) + 1e-5f);
                float dbv0 = 0.f, dbv1 = 0.f;
                if (HAS_DS){ dbv0 = __ldg(&dsb[colb]); dbv1 = __ldg(&dsb[colb+1]); }
                #pragma unroll
                for (int p = 0; p < 2; p++)
                    #pragma unroll
                    for (int h = 0; h < 2; h++){
                        int idx = h + 2*p;
                        int l = g + 8*idx;
                        if (l < 30){
                            float o0 = (acc[2*gg+p][nt][2*h]   - mux)*rsx*lnw4[idx] + lnb4[idx];
                            float o1 = (acc[2*gg+p][nt][2*h+1] - muy)*rsy*lnw4[idx] + lnb4[idx];
                            o0 = o0 > 0.f ? o0 : 0.f;
                            o1 = o1 > 0.f ? o1 : 0.f;
                            float r0, r1;
                            if (HAS_DS){
                                r0 = accd[2*gg+p][nt][2*h]   + dbv0;
                                r1 = accd[2*gg+p][nt][2*h+1] + dbv1;
                            } else {
                                float2 rr = *(const float2*)&resSrc[((size_t)((b0g+gg)*30) + l)*COUT + colb];
                                r0 = rr.x; r1 = rr.y;
                            }
                            float2 o; o.x = o0 + r0; o.y = o1 + r1;
                            *(float2*)&dstY[((size_t)((b0g+gg)*30) + l)*COUT + colb] = o;
                        }
                    }
            }
        }
    }
}

__global__ __launch_bounds__(512,1) void k_tcn0m(const float* __restrict__ lnw, const float* __restrict__ lnb){
    tcn_mma<256,256,1,256,512,false>(g_h, g_w0t, nullptr, nullptr, lnw, lnb, g_h, g_y0);
}
__global__ __launch_bounds__(512,1) void k_tcn1m(const float* __restrict__ dsb,
    const float* __restrict__ lnw, const float* __restrict__ lnb){
    tcn_mma<256,512,2,256,512,true>(g_y0, g_w1t, g_ds1t, dsb, lnw, lnb, nullptr, g_y1);
}
__global__ __launch_bounds__(512,1) void k_tcn2m(const float* __restrict__ dsb,
    const float* __restrict__ lnw, const float* __restrict__ lnb){
    tcn_mma<512,256,4,256,512,true>(g_y1, g_w2t, g_ds2t, dsb, lnw, lnb, nullptr, g_y2);
}

// ==================== generic TF32 mma GEMM (fc1), paired weights ====================
template<int K, int N, bool RELU>
__device__ __forceinline__ void mm_body(const float* __restrict__ A, const float* __restrict__ W,
    const float* __restrict__ bias, float* __restrict__ C)
{
    __shared__ __align__(16) float As[64][68];
    const int tid = threadIdx.x;
    const int warp = tid >> 5, lane = tid & 31;
    const int g = lane >> 2, tig = lane & 3;
    const int m0 = blockIdx.y*64, n0 = blockIdx.x*128;

    float acc[4][2][4];
    #pragma unroll
    for (int mt=0; mt<4; mt++)
        #pragma unroll
        for (int nt=0; nt<2; nt++)
            #pragma unroll
            for (int q=0; q<4; q++) acc[mt][nt][q] = 0.f;

    const int r = tid >> 2, cq = (tid & 3)*16;
    for (int k0 = 0; k0 < K; k0 += 64){
        __syncthreads();
        #pragma unroll
        for (int j = 0; j < 4; j++){
            float4 v = *(const float4*)&A[(size_t)(m0+r)*K + k0 + cq + j*4];
            As[r][cq+j*4+0] = tf32r(v.x); As[r][cq+j*4+1] = tf32r(v.y);
            As[r][cq+j*4+2] = tf32r(v.z); As[r][cq+j*4+3] = tf32r(v.w);
        }
        __syncthreads();
        #pragma unroll 2
        for (int kk = 0; kk < 8; kk++){
            unsigned Af[4][4];
            #pragma unroll
            for (int mt=0; mt<4; mt++){
                const float* base = &As[mt*16+g][kk*8+tig];
                Af[mt][0] = __float_as_uint(base[0]);
                Af[mt][1] = __float_as_uint(base[8*68]);
                Af[mt][2] = __float_as_uint(base[4]);
                Af[mt][3] = __float_as_uint(base[8*68+4]);
            }
            const float* Wp = W + ((size_t)(((k0>>3) + kk)*4 + tig)*N + n0 + warp*16)*2;
            #pragma unroll
            for (int nt=0; nt<2; nt++){
                u64 wv = __ldg((const u64*)(Wp + (nt*8 + g)*2));
                unsigned br0 = (unsigned)wv, br1 = (unsigned)(wv >> 32);
                #pragma unroll
                for (int mt=0; mt<4; mt++) mma8(acc[mt][nt], Af[mt], br0, br1);
            }
        }
    }
    #pragma unroll
    for (int mt=0; mt<4; mt++)
        #pragma unroll
        for (int nt=0; nt<2; nt++){
            int colb = n0 + warp*16 + nt*8 + 2*tig;
            float b0 = __ldg(&bias[colb]), b1 = __ldg(&bias[colb+1]);
            #pragma unroll
            for (int h2=0; h2<2; h2++){
                int row = m0 + mt*16 + g + 8*h2;
                float v0 = acc[mt][nt][2*h2]   + b0;
                float v1 = acc[mt][nt][2*h2+1] + b1;
                if (RELU){ v0 = v0 > 0.f ? v0 : 0.f; v1 = v1 > 0.f ? v1 : 0.f; }
                float2 o; o.x = v0; o.y = v1;
                *(float2*)&C[(size_t)row*N + colb] = o;
            }
        }
}
__global__ __launch_bounds__(256) void k_fc1mm(const float* __restrict__ bias){
    mm_body<7680,512,true>(g_y2, g_fc1p, bias, g_z1);
}

// ---- f32x2 tiled GEMM for fc2/fc3 ----
__device__ __forceinline__ void gemm_body(const float* __restrict__ A, const float* __restrict__ Bw,
    const float* __restrict__ bias, float* __restrict__ C, int M, int N, int K, bool doRelu)
{
    __shared__ __align__(16) float As2[16][68];
    __shared__ __align__(16) float Bs2[16][68];
    const int tid = threadIdx.x;
    const int tx = tid & 15, ty = tid >> 4;
    const int m0 = blockIdx.y*64, n0 = blockIdx.x*64;
    const int lm = tid >> 2, lk = (tid & 3)*4;
    u64 acc2[4][2];
    #pragma unroll
    for (int i = 0; i < 4; i++){ acc2[i][0] = 0ull; acc2[i][1] = 0ull; }

    for (int k0 = 0; k0 < K; k0 += 16){
        float4 av = *(const float4*)&A[(size_t)(m0+lm)*K + k0 + lk];
        float4 bv = make_float4(0.f,0.f,0.f,0.f);
        if (n0 + lm < N) bv = *(const float4*)&Bw[(size_t)(n0+lm)*K + k0 + lk];
        As2[lk+0][lm] = av.x; As2[lk+1][lm] = av.y; As2[lk+2][lm] = av.z; As2[lk+3][lm] = av.w;
        Bs2[lk+0][lm] = bv.x; Bs2[lk+1][lm] = bv.y; Bs2[lk+2][lm] = bv.z; Bs2[lk+3][lm] = bv.w;
        __syncthreads();
        #pragma unroll
        for (int k = 0; k < 16; k++){
            float4 a = *(const float4*)&As2[k][ty*4];
            u64 bp0 = *(const u64*)&Bs2[k][tx*4];
            u64 bp1 = *(const u64*)&Bs2[k][tx*4+2];
            u64 a0 = dup2(a.x), a1 = dup2(a.y), a2 = dup2(a.z), a3 = dup2(a.w);
            fma2(acc2[0][0], a0, bp0); fma2(acc2[0][1], a0, bp1);
            fma2(acc2[1][0], a1, bp0); fma2(acc2[1][1], a1, bp1);
            fma2(acc2[2][0], a2, bp0); fma2(acc2[2][1], a2, bp1);
            fma2(acc2[3][0], a3, bp0); fma2(acc2[3][1], a3, bp1);
        }
        __syncthreads();
    }
    #pragma unroll
    for (int i = 0; i < 4; i++){
        int row = m0 + ty*4 + i;
        float2 p0 = unp2(acc2[i][0]), p1 = unp2(acc2[i][1]);
        float vals[4] = {p0.x, p0.y, p1.x, p1.y};
        #pragma unroll
        for (int j = 0; j < 4; j++){
            int col = n0 + tx*4 + j;
            if (col < N){
                float v = vals[j] + __ldg(&bias[col]);
                if (doRelu) v = v > 0.f ? v : 0.f;
                C[(size_t)row*N + col] = v;
            }
        }
    }
}
__global__ __launch_bounds__(256) void k_fc2(const float* __restrict__ w, const float* __restrict__ bias){
    gemm_body(g_z1, w, bias, g_z2, 1024, 256, 512, true);
}
__global__ __launch_bounds__(256) void k_fc3(const float* __restrict__ w, const float* __restrict__ bias,
                                             float* __restrict__ out){
    gemm_body(g_z2, w, bias, out, 1024, 144, 256, false);
}

extern "C" void kernel_launch(void* const* d_in, const int* in_sizes, int n_in,
                              void* d_out, int out_size) {
    const float* x      = (const float*)d_in[0];
    const float* gWl    = (const float*)d_in[1];
    const float* gbl    = (const float*)d_in[2];
    const float* gWr    = (const float*)d_in[3];
    const float* gbr    = (const float*)d_in[4];
    const float* gatt   = (const float*)d_in[5];
    const float* gbias  = (const float*)d_in[6];
    const float* t0w    = (const float*)d_in[7];
    const float* ln0w   = (const float*)d_in[9];
    const float* ln0b   = (const float*)d_in[10];
    const float* t1w    = (const float*)d_in[11];
    const float* ln1w   = (const float*)d_in[13];
    const float* ln1b   = (const float*)d_in[14];
    const float* ds1w   = (const float*)d_in[15];
    const float* ds1b   = (const float*)d_in[16];
    const float* t2w    = (const float*)d_in[17];
    const float* ln2w   = (const float*)d_in[19];
    const float* ln2b   = (const float*)d_in[20];
    const float* ds2w   = (const float*)d_in[21];
    const float* ds2b   = (const float*)d_in[22];
    const float* fc1w   = (const float*)d_in[23];
    const float* fc1b   = (const float*)d_in[24];
    const float* fc2w   = (const float*)d_in[25];
    const float* fc2b   = (const float*)d_in[26];
    const float* fc3w   = (const float*)d_in[27];
    const float* fc3b   = (const float*)d_in[28];
    const int*   eidx   = (const int*)d_in[29];

    float* outp = (float*)d_out;
    bool full = (out_size >= 147456 + ETOT*4 + 2*ETOT);
    float* alphaOut = full ? (outp + 147456) : nullptr;
    float* eiOut    = full ? (outp + 147456 + ETOT*4) : nullptr;

    const int SM01 = 2*256*40*4;   // 81,920
    const int SM2  = 2*512*40*4;   // 163,840

    cudaFuncSetAttribute(k_gat,   cudaFuncAttributeMaxDynamicSharedMemorySize, 85*1024);
    cudaFuncSetAttribute(k_tcn0m, cudaFuncAttributeMaxDynamicSharedMemorySize, SM01);
    cudaFuncSetAttribute(k_tcn1m, cudaFuncAttributeMaxDynamicSharedMemorySize, SM01);
    cudaFuncSetAttribute(k_tcn2m, cudaFuncAttributeMaxDynamicSharedMemorySize, SM2);

    // Launch order chosen so the ncu -s/-c window (which previously captured
    // the 4th launch, k_tr_ds1) now captures k_tcn0m — a kernel that matters.
    k_tr_wlr<<<64,256>>>(gWl, gWr);                                   // 0
    k_gat<<<1024,256, 85*1024>>>(x, gbl, gbr, gatt, gbias, eidx, alphaOut); // 1
    k_tr_w0 <<<768,256>>>(t0w);                                       // 2
    k_tcn0m<<<512,512, SM01>>>(ln0w, ln0b);                           // 3  <- profiled slot
    k_tr_w1 <<<1536,256>>>(t1w);                                      // 4
    k_tr_ds1<<<512,256>>>(ds1w);                                      // 5
    k_tr_w2 <<<1536,256>>>(t2w);                                      // 6
    k_tr_ds2<<<512,256>>>(ds2w);                                      // 7
    k_tr_fc1<<<15360,256>>>(fc1w);                                    // 8
    if (eiOut) k_ei<<<1080,256>>>(eidx, eiOut);                       // 9

    k_tcn1m<<<512,512, SM01>>>(ds1b, ln1w, ln1b);
    k_tcn2m<<<512,512, SM2>>>(ds2b, ln2w, ln2b);

    { dim3 gd(4,16);  k_fc1mm<<<gd,256>>>(fc1b); }
    dim3 g2(4,16);  k_fc2<<<g2,256>>>(fc2w, fc2b);
    dim3 g3(3,16);  k_fc3<<<g3,256>>>(fc3w, fc3b, outp);
}